// round 15
// baseline (speedup 1.0000x reference)
#include <cuda_runtime.h>
#include <cuda_bf16.h>
#include <math.h>
#include <stdint.h>

// Problem constants
#define Hdim 1024
#define Idim 4096
#define NE   8
#define NT   2048
#define NSLOT 6144
#define SHOFF 4096

// ---------------- scratch ------------------------------------------------------
__device__ float g_hact[(size_t)NSLOT * Idim];      // tf32-rounded, k-permuted cols
__device__ float g_eo[(size_t)NSLOT * Hdim];
__device__ float g_upw_t[(size_t)9 * Idim * Hdim];  // W_up^T [n=I][k=H phys], tf32
__device__ float g_dnw_t[(size_t)9 * Hdim * Idim];  // W_dn^T [n=H][k=I phys], tf32
__device__ float g_x_c[(size_t)NT * Hdim];          // x, tf32-rounded, k-permuted
__device__ int   g_slot_token[NSLOT];
__device__ float g_slot_weight[NSLOT];
__device__ int   g_expert_off[10];
__device__ int   g_tok_slot[NT * 2];
__device__ int   g_tok_eidx[NT * 2];
__device__ float g_tok_w[NT * 2];

// ---------------- helpers ------------------------------------------------------
__device__ __forceinline__ uint32_t smem_u32(const void* p) {
  uint32_t r;
  asm("{ .reg .u64 t; cvta.to.shared.u64 t, %1; cvt.u32.u64 %0, t; }" : "=r"(r) : "l"(p));
  return r;
}
__device__ __forceinline__ void cp16(uint32_t s, const void* g) {
  asm volatile("cp.async.cg.shared.global [%0], [%1], 16;" :: "r"(s), "l"(g));
}
#define CP_COMMIT() asm volatile("cp.async.commit_group;" ::: "memory")
#define CP_WAIT(n)  asm volatile("cp.async.wait_group %0;" :: "n"(n) : "memory")

__device__ __forceinline__ uint32_t tf32cvt(float f) {
  uint32_t u;
  asm("cvt.rna.tf32.f32 %0, %1;" : "=r"(u) : "f"(f));
  return u;
}
// scalar-only mma wrapper: no address-taken arrays anywhere
__device__ __forceinline__ void mma8s(float& c0, float& c1, float& c2, float& c3,
                                      uint32_t a0, uint32_t a1, uint32_t a2, uint32_t a3,
                                      uint32_t b0, uint32_t b1) {
  asm volatile(
      "mma.sync.aligned.m16n8k8.row.col.f32.tf32.tf32.f32 "
      "{%0,%1,%2,%3},{%4,%5,%6,%7},{%8,%9},{%0,%1,%2,%3};"
      : "+f"(c0), "+f"(c1), "+f"(c2), "+f"(c3)
      : "r"(a0), "r"(a1), "r"(a2), "r"(a3), "r"(b0), "r"(b1));
}

// k-permutation within 8-blocks: logical w -> phys (pairs (q,q+4) -> (2q,2q+1))
__device__ __forceinline__ int kperm(int w) { return (w < 4) ? 2 * w : 2 * (w - 4) + 1; }

// ---------------- prep: weight transpose + tf32 + k-permute --------------------
// dst selected INSIDE device code (which: 0 = g_upw_t, 1 = g_dnw_t).
// Passing __device__ symbols as host-side kernel args resolves to the HOST
// shadow object (ATS-writable on this box) and trips the allocation guard.
__global__ __launch_bounds__(256) void wt_transpose(
    const float* __restrict__ Wexp, const float* __restrict__ Wsh,
    int which, int K, int N) {
  __shared__ float t[32][33];
  float* dst_base = (which == 0) ? g_upw_t : g_dnw_t;
  int e = blockIdx.z;
  const float* src = (e < NE) ? (Wexp + (size_t)e * K * N) : Wsh;
  float* dst = dst_base + (size_t)e * N * K;
  int n0 = blockIdx.x * 32, k0 = blockIdx.y * 32;
  int tx = threadIdx.x & 31, ty = threadIdx.x >> 5;
#pragma unroll
  for (int r = 0; r < 4; r++)
    t[ty + 8 * r][tx] = src[(size_t)(k0 + ty + 8 * r) * N + n0 + tx];
  __syncthreads();
  int kp = k0 + (tx & ~7) + kperm(tx & 7);
#pragma unroll
  for (int r = 0; r < 4; r++)
    dst[(size_t)(n0 + ty + 8 * r) * K + kp] =
        __uint_as_float(tf32cvt(t[tx][ty + 8 * r]));
}

// x -> g_x_c: tf32 + within-row k-permutation
__global__ __launch_bounds__(256) void x_perm(const float* __restrict__ x) {
  int i = blockIdx.x * blockDim.x + threadIdx.x;
  float4 v = ((const float4*)x)[i];
  int i4 = i * 4;
  int row = i4 >> 10, c = i4 & 1023;
  int base = c & ~7;
  int p = base + ((c & 4) ? 1 : 0);
  float* o = g_x_c + (size_t)row * Hdim;
  o[p + 0] = __uint_as_float(tf32cvt(v.x));
  o[p + 2] = __uint_as_float(tf32cvt(v.y));
  o[p + 4] = __uint_as_float(tf32cvt(v.z));
  o[p + 6] = __uint_as_float(tf32cvt(v.w));
}

// ---------------- gating -------------------------------------------------------
__global__ __launch_bounds__(256) void gate_kernel(
    const float* __restrict__ x, const float* __restrict__ gate_w,
    const float* __restrict__ gbias) {
  int warp = threadIdx.x >> 5, lane = threadIdx.x & 31;
  int t = blockIdx.x * 8 + warp;
  if (t >= NT) return;
  const float* xr = x + (size_t)t * Hdim;
  float s[NE] = {0.f,0.f,0.f,0.f,0.f,0.f,0.f,0.f};
  for (int k = lane; k < Hdim; k += 32) {
    float xv = xr[k];
    const float* gw = gate_w + k * NE;
#pragma unroll
    for (int e = 0; e < NE; e++) s[e] += xv * gw[e];
  }
#pragma unroll
  for (int e = 0; e < NE; e++)
#pragma unroll
    for (int o = 16; o > 0; o >>= 1) s[e] += __shfl_xor_sync(0xffffffffu, s[e], o);
  if (lane == 0) {
    float sc[NE];
#pragma unroll
    for (int e = 0; e < NE; e++) sc[e] = 1.0f / (1.0f + expf(-(s[e] + gbias[e])));
    int i0 = 0;
#pragma unroll
    for (int e = 1; e < NE; e++) if (sc[e] > sc[i0]) i0 = e;
    int i1 = (i0 == 0) ? 1 : 0;
#pragma unroll
    for (int e = 0; e < NE; e++) if (e != i0 && sc[e] > sc[i1]) i1 = e;
    float denom = sc[i0] + sc[i1] + 1e-6f;
    g_tok_eidx[t*2+0] = i0;  g_tok_eidx[t*2+1] = i1;
    g_tok_w[t*2+0] = sc[i0] / denom;  g_tok_w[t*2+1] = sc[i1] / denom;
  }
}

// ---------------- routing ------------------------------------------------------
__global__ __launch_bounds__(256) void route_kernel() {
  __shared__ int counts[NE];
  __shared__ int offs[NE + 1];
  int wid = threadIdx.x >> 5, lane = threadIdx.x & 31;
  if (wid < NE) {
    int cnt = 0;
    for (int t0 = 0; t0 < NT; t0 += 32) {
      int t = t0 + lane;
      bool m = (g_tok_eidx[t*2] == wid) || (g_tok_eidx[t*2+1] == wid);
      cnt += __popc(__ballot_sync(0xffffffffu, m));
    }
    if (lane == 0) counts[wid] = cnt;
  }
  __syncthreads();
  if (threadIdx.x == 0) {
    int o = 0;
    for (int e = 0; e < NE; e++) { offs[e] = o; g_expert_off[e] = o; o += counts[e]; }
    offs[NE] = o;
    g_expert_off[NE] = SHOFF;
    g_expert_off[NE + 1] = SHOFF + NT;
  }
  __syncthreads();
  if (wid < NE) {
    int pos = offs[wid];
    for (int t0 = 0; t0 < NT; t0 += 32) {
      int t = t0 + lane;
      int e0 = g_tok_eidx[t*2], e1 = g_tok_eidx[t*2+1];
      int k = (e0 == wid) ? 0 : ((e1 == wid) ? 1 : -1);
      unsigned mask = __ballot_sync(0xffffffffu, k >= 0);
      if (k >= 0) {
        int slot = pos + __popc(mask & ((1u << lane) - 1u));
        g_slot_token[slot] = t;
        g_slot_weight[slot] = g_tok_w[t*2+k];
        g_tok_slot[t*2+k] = slot;
      }
      pos += __popc(mask);
    }
  }
  for (int t = threadIdx.x; t < NT; t += blockDim.x) {
    g_slot_token[SHOFF + t] = t;
    g_slot_weight[SHOFF + t] = 1.0f;
  }
}

// ---------------- tf32 mma.sync grouped GEMM (LDS.64 fragments, 2-stage) -------
// 128x128 CTA tile, BK=32, 256 threads, 8 warps (4 M x 2 N), warp tile 32x64.
// A and B both k-fast (B pre-transposed), k-permuted: fragment pair = 1 LDS.64.
// Row pad 40 floats -> LDS.64 conflict-free. 2-stage cp.async (r7-proven loop).
// stage s (floats): A @ s*10240, B @ s*10240+5120. Total 81920 B, 1 CTA/SM.
#define SMEM_DYN 81920

template <int KDIM, int NDIM, bool GATHER, bool IS_UP>
__global__ __launch_bounds__(256, 1)
void moe_gemm(const float* __restrict__ Bexp, const float* __restrict__ Bsh) {
  extern __shared__ float sm[];
  int e = blockIdx.z;
  int start = g_expert_off[e];
  int count = g_expert_off[e + 1] - start;
  int m0 = blockIdx.y * 128;
  if (m0 >= count) return;
  int n0 = blockIdx.x * 128;

  const float* Wt = (IS_UP ? g_upw_t : g_dnw_t) + (size_t)e * KDIM * NDIM;
  const float* bias = (e < NE) ? (Bexp + (size_t)e * NDIM) : Bsh;

  const int tid  = threadIdx.x;
  const int lane = tid & 31;
  const int wid  = tid >> 5;
  const int warpM = wid & 3;
  const int warpN = wid >> 2;
  const int g  = lane >> 2;
  const int cq = lane & 3;

  // loader: 2 threads per row (128 rows), each 4 float4 of the 32-k chunk
  const int arow = tid >> 1;
  const int ahalf = tid & 1;
  int gmr = m0 + arow;
  int aidx = start + ((gmr < count) ? gmr : 0);
  const float* aptr;
  if (GATHER) aptr = g_x_c + (size_t)g_slot_token[aidx] * KDIM;
  else        aptr = g_hact + (size_t)aidx * KDIM;
  aptr += ahalf * 16;
  const float* bptr = Wt + (size_t)(n0 + arow) * KDIM + ahalf * 16;

  const uint32_t smb = smem_u32(sm);
  const uint32_t rowOff = (uint32_t)(arow * 160 + ahalf * 64);

  float acc[2][8][4];
#pragma unroll
  for (int mt = 0; mt < 2; mt++)
#pragma unroll
    for (int nt = 0; nt < 8; nt++)
#pragma unroll
      for (int q = 0; q < 4; q++) acc[mt][nt][q] = 0.0f;

  const int KT = KDIM / 32;

  auto load_stage = [&](int s, int kb) {
    uint32_t ab = smb + (uint32_t)s * 40960u + rowOff;
#pragma unroll
    for (int i = 0; i < 4; i++) cp16(ab + i * 16u, aptr + kb + i * 4);
    uint32_t bb = ab + 20480u;
#pragma unroll
    for (int i = 0; i < 4; i++) cp16(bb + i * 16u, bptr + kb + i * 4);
    CP_COMMIT();
  };

  load_stage(0, 0);

  for (int kt = 0; kt < KT; kt++) {
    if (kt + 1 < KT) { load_stage((kt + 1) & 1, (kt + 1) * 32); CP_WAIT(1); }
    else             { CP_WAIT(0); }
    __syncthreads();

    const uint32_t* As = (const uint32_t*)(sm + (kt & 1) * 10240);
    const uint32_t* Bs = As + 5120;
#pragma unroll
    for (int ks = 0; ks < 4; ks++) {
      int kb = ks * 8 + 2 * cq;              // physical pair (logical cq, cq+4)
      int r0 = (warpM * 32 + g) * 40 + kb;
      uint2 aL0 = *(const uint2*)&As[r0];            // rows g / g+8   (mt=0)
      uint2 aH0 = *(const uint2*)&As[r0 + 320];
      uint2 aL1 = *(const uint2*)&As[r0 + 640];      // rows +16 / +24 (mt=1)
      uint2 aH1 = *(const uint2*)&As[r0 + 960];
#pragma unroll
      for (int nt = 0; nt < 8; nt++) {
        int nc = warpN * 64 + nt * 8;
        uint2 b = *(const uint2*)&Bs[(nc + g) * 40 + kb];
        mma8s(acc[0][nt][0], acc[0][nt][1], acc[0][nt][2], acc[0][nt][3],
              aL0.x, aH0.x, aL0.y, aH0.y, b.x, b.y);
        mma8s(acc[1][nt][0], acc[1][nt][1], acc[1][nt][2], acc[1][nt][3],
              aL1.x, aH1.x, aL1.y, aH1.y, b.x, b.y);
      }
    }
    __syncthreads();
  }

  // ---- epilogue ----
  const int w0 = cq * 2, w1 = cq * 2 + 1;
  const int p0 = kperm(w0), p1 = kperm(w1);
#pragma unroll
  for (int mt = 0; mt < 2; mt++) {
#pragma unroll
    for (int half = 0; half < 2; half++) {
      int r = m0 + warpM * 32 + mt * 16 + g + half * 8;
      if (r >= count) continue;
      int slot = start + r;
      float wscale = IS_UP ? 0.0f : (0.1f * g_slot_weight[slot]);
      float* dstRow = IS_UP ? (g_hact + (size_t)slot * Idim)
                            : (g_eo   + (size_t)slot * Hdim);
#pragma unroll
      for (int nt = 0; nt < 8; nt++) {
        int colb = n0 + warpN * 64 + nt * 8;
        float v0 = acc[mt][nt][half * 2 + 0] + __ldg(bias + colb + w0);
        float v1 = acc[mt][nt][half * 2 + 1] + __ldg(bias + colb + w1);
        if (IS_UP) {
          v0 = 0.5f * v0 * (1.0f + erff(v0 * 0.70710678118654752440f));
          v1 = 0.5f * v1 * (1.0f + erff(v1 * 0.70710678118654752440f));
          dstRow[colb + p0] = __uint_as_float(tf32cvt(v0));
          dstRow[colb + p1] = __uint_as_float(tf32cvt(v1));
        } else {
          *(float2*)(dstRow + colb + w0) =
              make_float2(v0 * wscale, v1 * wscale);
        }
      }
    }
  }
}

// ---------------- combine ------------------------------------------------------
__global__ __launch_bounds__(256) void combine_kernel(float* __restrict__ out) {
  int t = blockIdx.x;
  int s0 = g_tok_slot[t*2+0], s1 = g_tok_slot[t*2+1];
  const float* r0 = g_eo + (size_t)(SHOFF + t) * Hdim;
  const float* ra = g_eo + (size_t)s0 * Hdim;
  const float* rb = g_eo + (size_t)s1 * Hdim;
  float v[4], mx = 0.0f;
#pragma unroll
  for (int i = 0; i < 4; i++) {
    int h = threadIdx.x + i * 256;
    float val = r0[h] + ra[h] + rb[h];
    v[i] = val;
    mx = fmaxf(mx, fabsf(val));
  }
#pragma unroll
  for (int o = 16; o > 0; o >>= 1) mx = fmaxf(mx, __shfl_xor_sync(0xffffffffu, mx, o));
  __shared__ float smax[8];
  __shared__ float bmax;
  if ((threadIdx.x & 31) == 0) smax[threadIdx.x >> 5] = mx;
  __syncthreads();
  if (threadIdx.x == 0) {
    float m = smax[0];
#pragma unroll
    for (int w = 1; w < 8; w++) m = fmaxf(m, smax[w]);
    bmax = m;
  }
  __syncthreads();
  float inv = 1.0f / (bmax + 1e-6f);
  float* op = out + (size_t)t * Hdim;
#pragma unroll
  for (int i = 0; i < 4; i++) op[threadIdx.x + i * 256] = v[i] * inv;
}

// ---------------- launch -------------------------------------------------------
extern "C" void kernel_launch(void* const* d_in, const int* in_sizes, int n_in,
                              void* d_out, int out_size) {
  const float* x       = (const float*)d_in[0];
  const float* gate_w  = (const float*)d_in[1];
  const float* bias    = (const float*)d_in[2];
  const float* up_w    = (const float*)d_in[3];
  const float* up_b    = (const float*)d_in[4];
  const float* down_w  = (const float*)d_in[5];
  const float* down_b  = (const float*)d_in[6];
  const float* sw_up   = (const float*)d_in[7];
  const float* sb_up   = (const float*)d_in[8];
  const float* sw_down = (const float*)d_in[9];
  const float* sb_down = (const float*)d_in[10];
  float* out = (float*)d_out;

  cudaFuncSetAttribute(moe_gemm<Hdim, Idim, true, true>,
                       cudaFuncAttributeMaxDynamicSharedMemorySize, SMEM_DYN);
  cudaFuncSetAttribute(moe_gemm<Idim, Hdim, false, false>,
                       cudaFuncAttributeMaxDynamicSharedMemorySize, SMEM_DYN);

  // prep: weights transposed+tf32+k-permuted; x tf32+k-permuted
  wt_transpose<<<dim3(Idim / 32, Hdim / 32, 9), 256>>>(up_w, sw_up, 0, Hdim, Idim);
  wt_transpose<<<dim3(Hdim / 32, Idim / 32, 9), 256>>>(down_w, sw_down, 1, Idim, Hdim);
  x_perm<<<NT * Hdim / 1024, 256>>>(x);

  gate_kernel<<<NT / 8, 256>>>(x, gate_w, bias);
  route_kernel<<<1, 256>>>();

  dim3 gUp(Idim / 128, NT / 128, 9);
  moe_gemm<Hdim, Idim, true, true><<<gUp, 256, SMEM_DYN>>>(up_b, sb_up);

  dim3 gDn(Hdim / 128, NT / 128, 9);
  moe_gemm<Idim, Hdim, false, false><<<gDn, 256, SMEM_DYN>>>(down_b, sb_down);

  combine_kernel<<<NT, 256>>>(out);
}

// round 17
// speedup vs baseline: 1.2093x; 1.2093x over previous
#include <cuda_runtime.h>
#include <cuda_bf16.h>
#include <math.h>
#include <stdint.h>

// Problem constants
#define Hdim 1024
#define Idim 4096
#define NE   8
#define NT   2048
#define NSLOT 6144
#define SHOFF 4096

// ---------------- scratch ------------------------------------------------------
__device__ float g_hact[(size_t)NSLOT * Idim];
__device__ float g_eo[(size_t)NSLOT * Hdim];
__device__ int   g_slot_token[NSLOT];
__device__ float g_slot_weight[NSLOT];
__device__ int   g_expert_off[10];
__device__ int   g_tok_slot[NT * 2];
__device__ int   g_tok_eidx[NT * 2];
__device__ float g_tok_w[NT * 2];

// ---------------- helpers ------------------------------------------------------
__device__ __forceinline__ uint32_t smem_u32(const void* p) {
  uint32_t r;
  asm("{ .reg .u64 t; cvta.to.shared.u64 t, %1; cvt.u32.u64 %0, t; }" : "=r"(r) : "l"(p));
  return r;
}
__device__ __forceinline__ void cp16(uint32_t s, const void* g) {
  asm volatile("cp.async.cg.shared.global [%0], [%1], 16;" :: "r"(s), "l"(g));
}
#define CP_COMMIT() asm volatile("cp.async.commit_group;" ::: "memory")
#define CP_WAIT(n)  asm volatile("cp.async.wait_group %0;" :: "n"(n) : "memory")

__device__ __forceinline__ uint32_t tf32cvt(float f) {
  uint32_t u;
  asm("cvt.rna.tf32.f32 %0, %1;" : "=r"(u) : "f"(f));
  return u;
}
__device__ __forceinline__ void mma8(float* c, const uint32_t* a, uint32_t b0, uint32_t b1) {
  asm volatile(
      "mma.sync.aligned.m16n8k8.row.col.f32.tf32.tf32.f32 "
      "{%0,%1,%2,%3},{%4,%5,%6,%7},{%8,%9},{%0,%1,%2,%3};"
      : "+f"(c[0]), "+f"(c[1]), "+f"(c[2]), "+f"(c[3])
      : "r"(a[0]), "r"(a[1]), "r"(a[2]), "r"(a[3]), "r"(b0), "r"(b1));
}

// ---------------- gating -------------------------------------------------------
__global__ __launch_bounds__(256) void gate_kernel(
    const float* __restrict__ x, const float* __restrict__ gate_w,
    const float* __restrict__ gbias) {
  int warp = threadIdx.x >> 5, lane = threadIdx.x & 31;
  int t = blockIdx.x * 8 + warp;
  if (t >= NT) return;
  const float* xr = x + (size_t)t * Hdim;
  float s[NE] = {0.f,0.f,0.f,0.f,0.f,0.f,0.f,0.f};
  for (int k = lane; k < Hdim; k += 32) {
    float xv = xr[k];
    const float* gw = gate_w + k * NE;
#pragma unroll
    for (int e = 0; e < NE; e++) s[e] += xv * gw[e];
  }
#pragma unroll
  for (int e = 0; e < NE; e++)
#pragma unroll
    for (int o = 16; o > 0; o >>= 1) s[e] += __shfl_xor_sync(0xffffffffu, s[e], o);
  if (lane == 0) {
    float sc[NE];
#pragma unroll
    for (int e = 0; e < NE; e++) sc[e] = 1.0f / (1.0f + expf(-(s[e] + gbias[e])));
    int i0 = 0;
#pragma unroll
    for (int e = 1; e < NE; e++) if (sc[e] > sc[i0]) i0 = e;
    int i1 = (i0 == 0) ? 1 : 0;
#pragma unroll
    for (int e = 0; e < NE; e++) if (e != i0 && sc[e] > sc[i1]) i1 = e;
    float denom = sc[i0] + sc[i1] + 1e-6f;
    g_tok_eidx[t*2+0] = i0;  g_tok_eidx[t*2+1] = i1;
    g_tok_w[t*2+0] = sc[i0] / denom;  g_tok_w[t*2+1] = sc[i1] / denom;
  }
}

// ---------------- routing ------------------------------------------------------
__global__ __launch_bounds__(256) void route_kernel() {
  __shared__ int counts[NE];
  __shared__ int offs[NE + 1];
  int wid = threadIdx.x >> 5, lane = threadIdx.x & 31;
  if (wid < NE) {
    int cnt = 0;
    for (int t0 = 0; t0 < NT; t0 += 32) {
      int t = t0 + lane;
      bool m = (g_tok_eidx[t*2] == wid) || (g_tok_eidx[t*2+1] == wid);
      cnt += __popc(__ballot_sync(0xffffffffu, m));
    }
    if (lane == 0) counts[wid] = cnt;
  }
  __syncthreads();
  if (threadIdx.x == 0) {
    int o = 0;
    for (int e = 0; e < NE; e++) { offs[e] = o; g_expert_off[e] = o; o += counts[e]; }
    offs[NE] = o;
    g_expert_off[NE] = SHOFF;
    g_expert_off[NE + 1] = SHOFF + NT;
  }
  __syncthreads();
  if (wid < NE) {
    int pos = offs[wid];
    for (int t0 = 0; t0 < NT; t0 += 32) {
      int t = t0 + lane;
      int e0 = g_tok_eidx[t*2], e1 = g_tok_eidx[t*2+1];
      int k = (e0 == wid) ? 0 : ((e1 == wid) ? 1 : -1);
      unsigned mask = __ballot_sync(0xffffffffu, k >= 0);
      if (k >= 0) {
        int slot = pos + __popc(mask & ((1u << lane) - 1u));
        g_slot_token[slot] = t;
        g_slot_weight[slot] = g_tok_w[t*2+k];
        g_tok_slot[t*2+k] = slot;
      }
      pos += __popc(mask);
    }
  }
  for (int t = threadIdx.x; t < NT; t += blockDim.x) {
    g_slot_token[SHOFF + t] = t;
    g_slot_weight[SHOFF + t] = 1.0f;
  }
}

// ---------------- tf32 mma.sync grouped GEMM (64x64 warp tiles) ----------------
// 128x128 CTA tile, BK=32, 128 threads, 4 warps (2 M x 2 N), warp tile 64x64.
// r7's exact smem layouts: A[2][128][36] @0 (stage stride 4608 floats),
// B[2][32][136] @9216 (stage stride 4352). Total 71680 B; 3 CTAs/SM target.
// smem reads/kt/CTA: A 128*32*2 + B 128*32*2 = 16384 words (r7: 24576).
#define SMEM_DYN 71680

template <int KDIM, int NDIM, bool GATHER, bool IS_UP>
__global__ __launch_bounds__(128, 3)
void moe_gemm(const float* __restrict__ Abase,
              const float* __restrict__ Wexp, const float* __restrict__ Bexp,
              const float* __restrict__ Wsh,  const float* __restrict__ Bsh) {
  extern __shared__ float sm[];
  int e = blockIdx.z;
  int start = g_expert_off[e];
  int count = g_expert_off[e + 1] - start;
  int m0 = blockIdx.y * 128;
  if (m0 >= count) return;
  int n0 = blockIdx.x * 128;

  const float* Bmat = (e < NE) ? (Wexp + (size_t)e * KDIM * NDIM) : Wsh;
  const float* bias = (e < NE) ? (Bexp + (size_t)e * NDIM) : Bsh;

  const int tid  = threadIdx.x;
  const int lane = tid & 31;
  const int wid  = tid >> 5;
  const int warpM = wid & 1;        // 0..1 -> 64-row strips
  const int warpN = wid >> 1;       // 0..1 -> 64-col strips
  const int g  = lane >> 2;
  const int cq = lane & 3;

  // A loader: 1 thread per row, 8 float4 each
  const int arow = tid;
  int gmr = m0 + arow;
  int aidx = start + ((gmr < count) ? gmr : 0);
  const float* aptr;
  if (GATHER) aptr = Abase + (size_t)g_slot_token[aidx] * KDIM;
  else        aptr = g_hact + (size_t)aidx * KDIM;

  const uint32_t smb = smem_u32(sm);
  const uint32_t aDst = smb + arow * 144u;

  float acc[4][8][4];
#pragma unroll
  for (int mt = 0; mt < 4; mt++)
#pragma unroll
    for (int nt = 0; nt < 8; nt++)
#pragma unroll
      for (int q = 0; q < 4; q++) acc[mt][nt][q] = 0.0f;

  const int KT = KDIM / 32;

  auto load_stage = [&](int s, int kb) {
    uint32_t ab = aDst + (uint32_t)s * 18432u;
#pragma unroll
    for (int i = 0; i < 8; i++) cp16(ab + i * 16u, aptr + kb + i * 4);
    uint32_t bb = smb + 36864u + (uint32_t)s * 17408u;
#pragma unroll
    for (int i = 0; i < 8; i++) {
      int idx = tid + 128 * i;
      int kr = idx >> 5, c4 = idx & 31;
      cp16(bb + kr * 544u + c4 * 16u,
           Bmat + (size_t)(kb + kr) * NDIM + n0 + c4 * 4);
    }
    CP_COMMIT();
  };

  load_stage(0, 0);

  for (int kt = 0; kt < KT; kt++) {
    if (kt + 1 < KT) { load_stage((kt + 1) & 1, (kt + 1) * 32); CP_WAIT(1); }
    else             { CP_WAIT(0); }
    __syncthreads();

    const float* As = sm + (kt & 1) * 4608;
    const float* Bs = sm + 9216 + (kt & 1) * 4352;
#pragma unroll
    for (int ks = 0; ks < 4; ks++) {
      int kb = ks * 8;
      uint32_t a[4][4];
#pragma unroll
      for (int mt = 0; mt < 4; mt++) {
        int r = warpM * 64 + mt * 16;
        a[mt][0] = tf32cvt(As[(r + g)     * 36 + kb + cq]);
        a[mt][1] = tf32cvt(As[(r + 8 + g) * 36 + kb + cq]);
        a[mt][2] = tf32cvt(As[(r + g)     * 36 + kb + cq + 4]);
        a[mt][3] = tf32cvt(As[(r + 8 + g) * 36 + kb + cq + 4]);
      }
#pragma unroll
      for (int nt = 0; nt < 8; nt++) {
        int nc = warpN * 64 + nt * 8;
        uint32_t b0 = tf32cvt(Bs[(kb + cq)     * 136 + nc + g]);
        uint32_t b1 = tf32cvt(Bs[(kb + cq + 4) * 136 + nc + g]);
        mma8(acc[0][nt], a[0], b0, b1);
        mma8(acc[1][nt], a[1], b0, b1);
        mma8(acc[2][nt], a[2], b0, b1);
        mma8(acc[3][nt], a[3], b0, b1);
      }
    }
    __syncthreads();
  }

  // ---- epilogue ----
#pragma unroll
  for (int mt = 0; mt < 4; mt++) {
#pragma unroll
    for (int half = 0; half < 2; half++) {
      int r = m0 + warpM * 64 + mt * 16 + g + half * 8;
      if (r >= count) continue;
      int slot = start + r;
      float wscale = IS_UP ? 0.0f : (0.1f * g_slot_weight[slot]);
      float* dstRow = IS_UP ? (g_hact + (size_t)slot * Idim)
                            : (g_eo   + (size_t)slot * Hdim);
#pragma unroll
      for (int nt = 0; nt < 8; nt++) {
        int col = n0 + warpN * 64 + nt * 8 + cq * 2;
        float v0 = acc[mt][nt][half * 2 + 0] + __ldg(bias + col);
        float v1 = acc[mt][nt][half * 2 + 1] + __ldg(bias + col + 1);
        if (IS_UP) {
          v0 = 0.5f * v0 * (1.0f + erff(v0 * 0.70710678118654752440f));
          v1 = 0.5f * v1 * (1.0f + erff(v1 * 0.70710678118654752440f));
        } else {
          v0 *= wscale;
          v1 *= wscale;
        }
        *(float2*)(dstRow + col) = make_float2(v0, v1);
      }
    }
  }
}

// ---------------- combine ------------------------------------------------------
__global__ __launch_bounds__(256) void combine_kernel(float* __restrict__ out) {
  int t = blockIdx.x;
  int s0 = g_tok_slot[t*2+0], s1 = g_tok_slot[t*2+1];
  const float* r0 = g_eo + (size_t)(SHOFF + t) * Hdim;
  const float* ra = g_eo + (size_t)s0 * Hdim;
  const float* rb = g_eo + (size_t)s1 * Hdim;
  float v[4], mx = 0.0f;
#pragma unroll
  for (int i = 0; i < 4; i++) {
    int h = threadIdx.x + i * 256;
    float val = r0[h] + ra[h] + rb[h];
    v[i] = val;
    mx = fmaxf(mx, fabsf(val));
  }
#pragma unroll
  for (int o = 16; o > 0; o >>= 1) mx = fmaxf(mx, __shfl_xor_sync(0xffffffffu, mx, o));
  __shared__ float smax[8];
  __shared__ float bmax;
  if ((threadIdx.x & 31) == 0) smax[threadIdx.x >> 5] = mx;
  __syncthreads();
  if (threadIdx.x == 0) {
    float m = smax[0];
#pragma unroll
    for (int w = 1; w < 8; w++) m = fmaxf(m, smax[w]);
    bmax = m;
  }
  __syncthreads();
  float inv = 1.0f / (bmax + 1e-6f);
  float* op = out + (size_t)t * Hdim;
#pragma unroll
  for (int i = 0; i < 4; i++) op[threadIdx.x + i * 256] = v[i] * inv;
}

// ---------------- launch -------------------------------------------------------
extern "C" void kernel_launch(void* const* d_in, const int* in_sizes, int n_in,
                              void* d_out, int out_size) {
  const float* x       = (const float*)d_in[0];
  const float* gate_w  = (const float*)d_in[1];
  const float* bias    = (const float*)d_in[2];
  const float* up_w    = (const float*)d_in[3];
  const float* up_b    = (const float*)d_in[4];
  const float* down_w  = (const float*)d_in[5];
  const float* down_b  = (const float*)d_in[6];
  const float* sw_up   = (const float*)d_in[7];
  const float* sb_up   = (const float*)d_in[8];
  const float* sw_down = (const float*)d_in[9];
  const float* sb_down = (const float*)d_in[10];
  float* out = (float*)d_out;

  cudaFuncSetAttribute(moe_gemm<Hdim, Idim, true, true>,
                       cudaFuncAttributeMaxDynamicSharedMemorySize, SMEM_DYN);
  cudaFuncSetAttribute(moe_gemm<Idim, Hdim, false, false>,
                       cudaFuncAttributeMaxDynamicSharedMemorySize, SMEM_DYN);

  gate_kernel<<<NT / 8, 256>>>(x, gate_w, bias);
  route_kernel<<<1, 256>>>();

  dim3 gUp(Idim / 128, NT / 128, 9);
  moe_gemm<Hdim, Idim, true, true><<<gUp, 128, SMEM_DYN>>>(x, up_w, up_b, sw_up, sb_up);

  dim3 gDn(Hdim / 128, NT / 128, 9);
  moe_gemm<Idim, Hdim, false, false><<<gDn, 128, SMEM_DYN>>>(nullptr, down_w, down_b, sw_down, sb_down);

  combine_kernel<<<NT, 256>>>(out);
}